// round 5
// baseline (speedup 1.0000x reference)
#include <cuda_runtime.h>
#include <cuda_bf16.h>
#include <cstdint>

#define VOCAB 50257
#define BATCH 512
#define SEQ   512
#define NCTA  512
#define NTHR  512

// Interleaved weight table: g_Wt[v] = (W[0][v], W[1][v]). One 32B sector
// serves both classes per token -> minimum wavefront count (262K).
__device__ float2 g_Wt[VOCAB];
// Monotonic grid-barrier counter (epoch = old/NCTA), replay-safe.
__device__ unsigned long long g_bar;

__global__ __launch_bounds__(NTHR) void bow_onepass_kernel(
    const int* __restrict__ ids,
    const float* __restrict__ W,     // [2, VOCAB]
    const float* __restrict__ bias,  // [2]
    float* __restrict__ out)         // [BATCH, 2]
{
    const int row = blockIdx.x;
    const int t   = threadIdx.x;

    // ---- Phase 1: cooperative pack (each thread packs <= 1 entry) ----
    {
        int i = row * NTHR + t;           // 0 .. 262143, covers VOCAB
        if (i < VOCAB)
            g_Wt[i] = make_float2(__ldg(W + i), __ldg(W + VOCAB + i));
    }

    // ---- Software grid barrier (all 512 CTAs resident in one wave) ----
    __syncthreads();
    if (t == 0) {
        __threadfence();                               // release pack stores
        unsigned long long old = atomicAdd(&g_bar, 1ULL);
        unsigned long long target = (old / NCTA + 1ULL) * NCTA;
        volatile unsigned long long* p = &g_bar;
        while (*p < target) { }
        __threadfence();                               // acquire peers' stores
    }
    __syncthreads();                                    // CTA observes barrier

    // ---- Phase 2: one token per thread, one packed gather ----
    const int id = __ldg(ids + row * SEQ + t);
    float2 w = g_Wt[id];
    const float m = (id != 0) ? 1.0f : 0.0f;
    float s0 = m * w.x;
    float s1 = m * w.y;

    // Warp reduce
    #pragma unroll
    for (int o = 16; o > 0; o >>= 1) {
        s0 += __shfl_xor_sync(0xFFFFFFFFu, s0, o);
        s1 += __shfl_xor_sync(0xFFFFFFFFu, s1, o);
    }

    __shared__ float sm0[16], sm1[16];
    const int wid = t >> 5, lid = t & 31;
    if (lid == 0) { sm0[wid] = s0; sm1[wid] = s1; }
    __syncthreads();

    if (wid == 0) {
        float r0 = (lid < 16) ? sm0[lid] : 0.f;
        float r1 = (lid < 16) ? sm1[lid] : 0.f;
        #pragma unroll
        for (int o = 8; o > 0; o >>= 1) {
            r0 += __shfl_xor_sync(0xFFFFFFFFu, r0, o);
            r1 += __shfl_xor_sync(0xFFFFFFFFu, r1, o);
        }
        if (lid == 0) {
            out[row * 2 + 0] = r0 + __ldg(bias + 0);
            out[row * 2 + 1] = r1 + __ldg(bias + 1);
        }
    }
}

extern "C" void kernel_launch(void* const* d_in, const int* in_sizes, int n_in,
                              void* d_out, int out_size) {
    const int*   ids  = (const int*)d_in[0];    // [512, 512] int32
    const float* W    = (const float*)d_in[1];  // [2, 50257] float32
    const float* bias = (const float*)d_in[2];  // [2] float32
    float* out = (float*)d_out;                 // [512, 2] float32

    bow_onepass_kernel<<<NCTA, NTHR>>>(ids, W, bias, out);
}

// round 6
// speedup vs baseline: 1.0036x; 1.0036x over previous
#include <cuda_runtime.h>
#include <cuda_bf16.h>
#include <cstdint>

#define VOCAB 50257
#define BATCH 512
#define SEQ   512

// Interleaved weight table: g_Wt[v] = (W[0][v], W[1][v]). One 32B sector /
// one 128B line serves both classes per token -> minimal L1tex wavefronts.
__device__ float2 g_Wt[VOCAB];

__global__ __launch_bounds__(512) void pack_w_kernel(const float* __restrict__ W) {
    int i = blockIdx.x * blockDim.x + threadIdx.x;
    if (i < VOCAB)
        g_Wt[i] = make_float2(__ldg(W + i), __ldg(W + VOCAB + i));
}

// One CTA per batch row, one thread per token, one packed float2 gather.
// 512x512 shape measured at ~75-81% occupancy -> L1tex queue stays full.
__global__ __launch_bounds__(512) void bow_gather_kernel(
    const int* __restrict__ ids,
    const float* __restrict__ bias,
    float* __restrict__ out)
{
    const int row = blockIdx.x;
    const int t   = threadIdx.x;

    const int id = __ldg(ids + row * SEQ + t);

    // Branch-free: id==0 (pad) gathers g_Wt[0] then masks it out.
    float2 w = g_Wt[id];
    const float m = (id != 0) ? 1.0f : 0.0f;
    float s0 = m * w.x;
    float s1 = m * w.y;

    // Warp reduce
    #pragma unroll
    for (int o = 16; o > 0; o >>= 1) {
        s0 += __shfl_xor_sync(0xFFFFFFFFu, s0, o);
        s1 += __shfl_xor_sync(0xFFFFFFFFu, s1, o);
    }

    __shared__ float sm0[16], sm1[16];
    const int wid = t >> 5, lid = t & 31;
    if (lid == 0) { sm0[wid] = s0; sm1[wid] = s1; }
    __syncthreads();

    if (wid == 0) {
        float r0 = (lid < 16) ? sm0[lid] : 0.f;
        float r1 = (lid < 16) ? sm1[lid] : 0.f;
        #pragma unroll
        for (int o = 8; o > 0; o >>= 1) {
            r0 += __shfl_xor_sync(0xFFFFFFFFu, r0, o);
            r1 += __shfl_xor_sync(0xFFFFFFFFu, r1, o);
        }
        if (lid == 0) {
            out[row * 2 + 0] = r0 + __ldg(bias + 0);
            out[row * 2 + 1] = r1 + __ldg(bias + 1);
        }
    }
}

extern "C" void kernel_launch(void* const* d_in, const int* in_sizes, int n_in,
                              void* d_out, int out_size) {
    const int*   ids  = (const int*)d_in[0];    // [512, 512] int32
    const float* W    = (const float*)d_in[1];  // [2, 50257] float32
    const float* bias = (const float*)d_in[2];  // [2] float32
    float* out = (float*)d_out;                 // [512, 2] float32

    pack_w_kernel<<<(VOCAB + 511) / 512, 512>>>(W);
    bow_gather_kernel<<<BATCH, 512>>>(ids, bias, out);
}

// round 10
// speedup vs baseline: 1.0294x; 1.0257x over previous
#include <cuda_runtime.h>
#include <cuda_bf16.h>
#include <cstdint>

#define VOCAB 50257
#define BATCH 512
#define SEQ   512

// Interleaved weight table: g_Wt[v] = (W[0][v], W[1][v]).
__device__ float2 g_Wt[VOCAB];

__global__ __launch_bounds__(512) void pack_w_kernel(const float* __restrict__ W) {
    int i = blockIdx.x * blockDim.x + threadIdx.x;
    if (i < VOCAB)
        g_Wt[i] = make_float2(__ldg(W + i), __ldg(W + VOCAB + i));
    // Let the dependent gather kernel begin launching now; its
    // cudaGridDependencySynchronize() still guarantees our stores are visible.
    cudaTriggerProgrammaticLaunchCompletion();
}

// 512 CTAs x 256 threads, 2 tokens/thread (best measured shape, 5.25us).
// Pre-dependency phase: stream ids from DRAM (overlaps pack kernel).
// Post-sync phase: packed float2 gathers, branch-free.
__global__ __launch_bounds__(256) void bow_gather_kernel(
    const int* __restrict__ ids,
    const float* __restrict__ bias,
    float* __restrict__ out)
{
    const int row = blockIdx.x;
    const int t   = threadIdx.x;   // 0..255

    // ---- Pre-dependency work: id loads do not touch g_Wt ----
    const int2 v = reinterpret_cast<const int2*>(ids + row * SEQ)[t];
    const float m0 = (v.x != 0) ? 1.0f : 0.0f;
    const float m1 = (v.y != 0) ? 1.0f : 0.0f;

    // ---- Wait for pack kernel's stores to be visible ----
    cudaGridDependencySynchronize();

    float2 w0 = g_Wt[v.x];
    float2 w1 = g_Wt[v.y];

    float s0 = fmaf(m0, w0.x, m1 * w1.x);
    float s1 = fmaf(m0, w0.y, m1 * w1.y);

    // Warp reduce
    #pragma unroll
    for (int o = 16; o > 0; o >>= 1) {
        s0 += __shfl_xor_sync(0xFFFFFFFFu, s0, o);
        s1 += __shfl_xor_sync(0xFFFFFFFFu, s1, o);
    }

    __shared__ float sm0[8], sm1[8];
    const int wid = t >> 5, lid = t & 31;
    if (lid == 0) { sm0[wid] = s0; sm1[wid] = s1; }
    __syncthreads();

    if (wid == 0 && lid < 8) {
        float r0 = sm0[lid];
        float r1 = sm1[lid];
        #pragma unroll
        for (int o = 4; o > 0; o >>= 1) {
            r0 += __shfl_xor_sync(0x000000FFu, r0, o);
            r1 += __shfl_xor_sync(0x000000FFu, r1, o);
        }
        if (lid == 0) {
            out[row * 2 + 0] = r0 + __ldg(bias + 0);
            out[row * 2 + 1] = r1 + __ldg(bias + 1);
        }
    }
}

extern "C" void kernel_launch(void* const* d_in, const int* in_sizes, int n_in,
                              void* d_out, int out_size) {
    const int*   ids  = (const int*)d_in[0];    // [512, 512] int32
    const float* W    = (const float*)d_in[1];  // [2, 50257] float32
    const float* bias = (const float*)d_in[2];  // [2] float32
    float* out = (float*)d_out;                 // [512, 2] float32

    pack_w_kernel<<<(VOCAB + 511) / 512, 512>>>(W);

    // Launch gather with Programmatic Stream Serialization (PDL): it may begin
    // while pack drains; cudaGridDependencySynchronize() inside enforces the
    // data dependency.
    cudaLaunchConfig_t cfg = {};
    cfg.gridDim  = dim3(BATCH, 1, 1);
    cfg.blockDim = dim3(256, 1, 1);
    cfg.dynamicSmemBytes = 0;
    cfg.stream = 0;
    cudaLaunchAttribute attrs[1];
    attrs[0].id = cudaLaunchAttributeProgrammaticStreamSerialization;
    attrs[0].val.programmaticStreamSerializationAllowed = 1;
    cfg.attrs = attrs;
    cfg.numAttrs = 1;
    cudaLaunchKernelEx(&cfg, bow_gather_kernel, ids, bias, (float*)d_out);
}